// round 4
// baseline (speedup 1.0000x reference)
#include <cuda_runtime.h>

// Diverse beam search step.
// Inputs (metadata order):
//  0 logprobs            f32 [B,K,V]
//  1 beam_seq            i32 [B,T,K]
//  2 beam_seq_logprobs   f32 [B,T,K]
//  3 beam_logprobs_sum   f32 [B,K]
//  4 state               f32 [2,2,B,K,H]
//  5 prev_decisions      i32 [B,16,K]
//  6 t                   int scalar (read low 32 bits)
// Output: f32 concat of (new_beam_seq, new_beam_seq_logprobs, sel_p, new_state)

#define Bn 128
#define Kn 16
#define Vn 50257
#define Tn 20
#define Hn 512
#define NPREV 256                  // 16*K tokens per batch
#define NBMW ((Vn + 31) / 32)      // 1571 bitmap words
#define NT 256
#define CH 4096                    // elements per chunk (4 float4 per thread)
#define WU 1024                    // warm-up elements
#define BUFSZ 1056

#define OFF_LPS   (Bn * Tn * Kn)                 // 40960
#define OFF_SELP  (2 * Bn * Tn * Kn)             // 81920
#define OFF_STATE (2 * Bn * Tn * Kn + Bn * Kn)   // 83968

__device__ unsigned long long g_cand[Bn * Kn * 16];  // per-beam top16 keys, rank-desc
__device__ int g_q[Bn * Kn];                         // selected source beam per (b, rank)

// ---------------- order-preserving float <-> uint32 ----------------
__device__ __forceinline__ unsigned ford(float x) {
    unsigned u = __float_as_uint(x);
    return u ^ (((unsigned)((int)u >> 31)) | 0x80000000u);
}
__device__ __forceinline__ float finv(unsigned o) {
    unsigned u = (o & 0x80000000u) ? (o ^ 0x80000000u) : ~o;
    return __uint_as_float(u);
}

// ---------------- per-beam streaming top-16 over V ----------------
// Hot loop filters on RAW values vs the (penalized) running 16th-best value.
// Penalties only lower values, so this is a conservative superset filter.
// EOS (-1000) and diversity penalties + exact key construction
// (key = ord(aug)<<32 | ~v : desc value, asc index == jax.lax.top_k order)
// are applied only in the rare merge path.
__global__ __launch_bounds__(NT) void k_beam_topk(const float* __restrict__ lp,
                                                  const int* __restrict__ prev) {
    __shared__ unsigned bm[NBMW];
    __shared__ int prevtok[NPREV];
    __shared__ unsigned long long buf[BUFSZ];
    __shared__ unsigned long long stop[16];
    __shared__ float thr_s;
    __shared__ int nbuf_s, ntop_s;

    const int tid = threadIdx.x;
    const int bk = blockIdx.x;
    const int b = bk >> 4;
    const long rowbase = (long)bk * Vn;
    const float* row = lp + rowbase;
    const float4* lp4 = (const float4*)lp;

    for (int i = tid; i < NBMW; i += NT) bm[i] = 0u;
    if (tid == 0) { nbuf_s = 0; ntop_s = 0; thr_s = 0.0f; }
    __syncthreads();
    {
        int tok = prev[b * NPREV + tid];   // NPREV == NT
        prevtok[tid] = tok;
        atomicOr(&bm[tok >> 5], 1u << (tok & 31));
    }

    // alignment: (rowbase + a) % 4 == 0 ; Vn % 4 == 1 -> a = (-bk) & 3
    const int a = (4 - (bk & 3)) & 3;
    const int M0 = a + WU;

    // ---- warm-up: elements [0, a) scalar + [a, a+WU) vectorized, append all ----
    {
        float4 x = lp4[((rowbase + a) >> 2) + tid];
        int v = a + 4 * tid;
        buf[4 * tid + 0] = ((unsigned long long)__float_as_uint(x.x) << 32) | (unsigned)(v + 0);
        buf[4 * tid + 1] = ((unsigned long long)__float_as_uint(x.y) << 32) | (unsigned)(v + 1);
        buf[4 * tid + 2] = ((unsigned long long)__float_as_uint(x.z) << 32) | (unsigned)(v + 2);
        buf[4 * tid + 3] = ((unsigned long long)__float_as_uint(x.w) << 32) | (unsigned)(v + 3);
        if (tid < a)
            buf[WU + tid] = ((unsigned long long)__float_as_uint(row[tid]) << 32) | (unsigned)tid;
    }
    __syncthreads();

    // merge lambda-ish macro body executed by thread 0
#define MERGE_BUF(NENT)                                                              \
    {                                                                                \
        int n = (NENT); if (n > BUFSZ) n = BUFSZ;                                    \
        int ntop = ntop_s;                                                           \
        for (int i = 0; i < n; i++) {                                                \
            unsigned long long e = buf[i];                                           \
            unsigned v = (unsigned)e;                                                \
            float x = __uint_as_float((unsigned)(e >> 32));                          \
            if (v == (unsigned)(Vn - 1)) x -= 1000.0f;                               \
            if ((bm[v >> 5] >> (v & 31)) & 1u) {                                     \
                int cc = 0;                                                          \
                for (int m = 0; m < NPREV; m++) cc += (prevtok[m] == (int)v);        \
                x -= 0.5f * (float)cc;                                               \
            }                                                                        \
            unsigned long long key =                                                 \
                ((unsigned long long)ford(x) << 32) | (unsigned)(0xFFFFFFFFu - v);   \
            if (ntop < 16) {                                                         \
                int p = ntop++;                                                      \
                while (p > 0 && stop[p - 1] < key) { stop[p] = stop[p - 1]; p--; }   \
                stop[p] = key;                                                       \
            } else if (key > stop[15]) {                                             \
                int p = 15;                                                          \
                while (p > 0 && stop[p - 1] < key) { stop[p] = stop[p - 1]; p--; }   \
                stop[p] = key;                                                       \
            }                                                                        \
        }                                                                            \
        ntop_s = ntop;                                                               \
        nbuf_s = 0;                                                                  \
        thr_s = finv((unsigned)(stop[15] >> 32));                                    \
    }

    if (tid == 0) MERGE_BUF(WU + a);
    __syncthreads();
    float thr = thr_s;

    // ---- main: full chunks of CH elements, filter-only hot loop ----
    const int nfull = (Vn - M0) / CH;
    for (int c = 0; c < nfull; c++) {
        const int cb = M0 + c * CH;
        const long f0 = (rowbase + cb) >> 2;
        float4 x0 = __ldcs(&lp4[f0 + 0 * NT + tid]);
        float4 x1 = __ldcs(&lp4[f0 + 1 * NT + tid]);
        float4 x2 = __ldcs(&lp4[f0 + 2 * NT + tid]);
        float4 x3 = __ldcs(&lp4[f0 + 3 * NT + tid]);
#define CHECK4(X, J)                                                                  \
        {                                                                             \
            float m01 = fmaxf((X).x, (X).y), m23 = fmaxf((X).z, (X).w);               \
            if (fmaxf(m01, m23) >= thr) {                                             \
                int v = cb + 4 * ((J) * NT + tid);                                    \
                if ((X).x >= thr) { int p = atomicAdd(&nbuf_s, 1); if (p < BUFSZ)     \
                    buf[p] = ((unsigned long long)__float_as_uint((X).x) << 32) | (unsigned)(v + 0); } \
                if ((X).y >= thr) { int p = atomicAdd(&nbuf_s, 1); if (p < BUFSZ)     \
                    buf[p] = ((unsigned long long)__float_as_uint((X).y) << 32) | (unsigned)(v + 1); } \
                if ((X).z >= thr) { int p = atomicAdd(&nbuf_s, 1); if (p < BUFSZ)     \
                    buf[p] = ((unsigned long long)__float_as_uint((X).z) << 32) | (unsigned)(v + 2); } \
                if ((X).w >= thr) { int p = atomicAdd(&nbuf_s, 1); if (p < BUFSZ)     \
                    buf[p] = ((unsigned long long)__float_as_uint((X).w) << 32) | (unsigned)(v + 3); } \
            }                                                                         \
        }
        CHECK4(x0, 0) CHECK4(x1, 1) CHECK4(x2, 2) CHECK4(x3, 3)
        __syncthreads();
        if (tid == 0 && nbuf_s) MERGE_BUF(nbuf_s);
        __syncthreads();
        thr = thr_s;
    }

    // ---- tail (contains v = V-1) ----
    for (int v = M0 + nfull * CH + tid; v < Vn; v += NT) {
        float x = row[v];
        if (x >= thr) {
            int p = atomicAdd(&nbuf_s, 1);
            if (p < BUFSZ)
                buf[p] = ((unsigned long long)__float_as_uint(x) << 32) | (unsigned)v;
        }
    }
    __syncthreads();
    if (tid == 0 && nbuf_s) MERGE_BUF(nbuf_s);
    __syncthreads();
    if (tid < 16) g_cand[bk * 16 + tid] = stop[tid];
#undef CHECK4
#undef MERGE_BUF
}

// ---------------- global top-16 over KxK candidates + seq outputs ----------------
__global__ __launch_bounds__(NT) void k_select(const float* __restrict__ lp,
                                               const int* __restrict__ beam_seq,
                                               const float* __restrict__ beam_lps,
                                               const float* __restrict__ sums,
                                               const int* __restrict__ d_t,
                                               float* __restrict__ out) {
    __shared__ unsigned long long skey[NT];
    __shared__ int sel_i[16];
    __shared__ float sel_v[16];
    __shared__ int q_s[16], tok_s[16];
    __shared__ float r_s[16];

    const int b = blockIdx.x, tid = threadIdx.x;
    {
        unsigned long long ck = g_cand[b * 256 + tid];
        float aug = finv((unsigned)(ck >> 32));
        float p = sums[b * Kn + (tid >> 4)] + aug;
        // flat index tid = k*K + c  -> matches jax reshape(B, K*K) tie order
        skey[tid] = ((unsigned long long)ford(p) << 32) | (unsigned)(0xFFFFFFFFu - (unsigned)tid);
    }
    __syncthreads();
    // rank-based selection: keys unique -> rank = #greater; rank<16 wins
    {
        unsigned long long mine = skey[tid];
        int rank = 0;
#pragma unroll 8
        for (int i = 0; i < NT; i++) rank += (skey[i] > mine);
        if (rank < 16) { sel_i[rank] = tid; sel_v[rank] = finv((unsigned)(mine >> 32)); }
    }
    __syncthreads();
    if (tid < 16) {
        int ii = sel_i[tid];
        int q = ii >> 4;
        unsigned long long ck = g_cand[b * 256 + ii];
        int tok = (int)(0xFFFFFFFFu - (unsigned)(ck & 0xFFFFFFFFull));
        float r = lp[(long)(b * Kn + q) * Vn + tok];   // unaugmented, exact
        if (tok == Vn - 1) r -= 1000.0f;
        q_s[tid] = q; tok_s[tid] = tok; r_s[tid] = r;
        g_q[b * Kn + tid] = q;
        out[OFF_SELP + b * Kn + tid] = sel_v[tid];
    }
    __syncthreads();
    const int t = d_t[0];   // low 32 bits: correct for i32 or little-endian i64
    for (int idx = tid; idx < Tn * Kn; idx += NT) {
        int tt = idx >> 4, k = idx & 15;
        float vs, vl;
        if (tt < t) {
            int q = q_s[k];
            vs = (float)beam_seq[(b * Tn + tt) * Kn + q];
            vl = beam_lps[(b * Tn + tt) * Kn + q];
        } else if (tt == t) {
            vs = (float)tok_s[k];
            vl = r_s[k];
        } else {
            vs = (float)beam_seq[(b * Tn + tt) * Kn + k];
            vl = beam_lps[(b * Tn + tt) * Kn + k];
        }
        out[(b * Tn + tt) * Kn + k] = vs;
        out[OFF_LPS + (b * Tn + tt) * Kn + k] = vl;
    }
}

// ---------------- state gather along beam dim (float4) ----------------
__global__ void k_state(const float4* __restrict__ st, float4* __restrict__ dst) {
    int idx = blockIdx.x * blockDim.x + threadIdx.x;   // over S*L*B*K*H/4 = 1048576
    int h4 = idx & (Hn / 4 - 1);
    int rowid = idx >> 7;              // H/4 = 128
    int k = rowid & (Kn - 1);
    int bsl = rowid >> 4;              // (s*L+l)*B + b
    int b = bsl & (Bn - 1);
    int q = __ldg(&g_q[b * Kn + k]);
    dst[idx] = st[((bsl << 4) + q) * (Hn / 4) + h4];
}

extern "C" void kernel_launch(void* const* d_in, const int* in_sizes, int n_in,
                              void* d_out, int out_size) {
    const float* lp   = (const float*)d_in[0];
    const int*   seq  = (const int*)d_in[1];
    const float* lps  = (const float*)d_in[2];
    const float* sums = (const float*)d_in[3];
    const float* st   = (const float*)d_in[4];
    const int*   prev = (const int*)d_in[5];
    const int*   dt   = (const int*)d_in[6];
    float* out = (float*)d_out;

    k_beam_topk<<<Bn * Kn, NT>>>(lp, prev);
    k_select<<<Bn, NT>>>(lp, seq, lps, sums, dt, out);
    k_state<<<(2 * 2 * Bn * Kn * (Hn / 4)) / NT, NT>>>((const float4*)st,
                                                       (float4*)(out + OFF_STATE));
}

// round 6
// speedup vs baseline: 2.4386x; 2.4386x over previous
#include <cuda_runtime.h>

// Diverse beam search step.
// Inputs (metadata order):
//  0 logprobs            f32 [B,K,V]
//  1 beam_seq            i32 [B,T,K]
//  2 beam_seq_logprobs   f32 [B,T,K]
//  3 beam_logprobs_sum   f32 [B,K]
//  4 state               f32 [2,2,B,K,H]
//  5 prev_decisions      i32 [B,16,K]
//  6 t                   int scalar (read low 32 bits)
// Output: f32 concat of (new_beam_seq, new_beam_seq_logprobs, sel_p, new_state)

#define Bn 128
#define Kn 16
#define Vn 50257
#define Tn 20
#define Hn 512
#define NPREV 256                  // 16*K tokens per batch
#define NBMW ((Vn + 31) / 32)      // 1571 bitmap words
#define NT 256
#define WU 4096                    // warm-up elements (16 per thread)
#define BUFSZ 2048

#define OFF_LPS   (Bn * Tn * Kn)                 // 40960
#define OFF_SELP  (2 * Bn * Tn * Kn)             // 81920
#define OFF_STATE (2 * Bn * Tn * Kn + Bn * Kn)   // 83968

__device__ unsigned long long g_cand[Bn * Kn * 16];  // per-beam top16 keys, rank-desc
__device__ int g_q[Bn * Kn];                         // selected source beam per (b, rank)

// ---------------- order-preserving float <-> uint32 ----------------
__device__ __forceinline__ unsigned ford(float x) {
    unsigned u = __float_as_uint(x);
    return u ^ (((unsigned)((int)u >> 31)) | 0x80000000u);
}
__device__ __forceinline__ float finv(unsigned o) {
    unsigned u = (o & 0x80000000u) ? (o ^ 0x80000000u) : ~o;
    return __uint_as_float(u);
}

// ---------------- per-beam streaming top-16 over V ----------------
// Phase 1: conservative fixed threshold thr <= true 16th-best penalized value
//   (warm-up maxes with worst-case penalty 0.5*256=128 applied to bitmap hits,
//    then exact 16th of the 256 thread-maxes). >=16 elements always pass.
// Phase 2: barrier-free filtered sweep of the whole row; rare passers appended
//   (raw value) to a shared buffer via atomic.
// Phase 3: penalties + exact key = ord(aug)<<32 | ~v (desc value, asc index ==
//   jax.lax.top_k tie order) applied in parallel; thread 0 merges to top-16.
__global__ __launch_bounds__(NT) void k_beam_topk(const float* __restrict__ lp,
                                                  const int* __restrict__ prev) {
    __shared__ unsigned bm[NBMW];
    __shared__ int prevtok[NPREV];
    __shared__ unsigned long long buf[BUFSZ];
    __shared__ unsigned wmax[NT];
    __shared__ unsigned long long stop[16];
    __shared__ float thr_s;
    __shared__ int nbuf_s;

    const int tid = threadIdx.x;
    const int bk = blockIdx.x;
    const int b = bk >> 4;
    const long rowbase = (long)bk * Vn;
    const float* row = lp + rowbase;
    const float4* lp4 = (const float4*)lp;

    for (int i = tid; i < NBMW; i += NT) bm[i] = 0u;
    if (tid == 0) nbuf_s = 0;
    __syncthreads();
    {
        int tok = prev[b * NPREV + tid];   // NPREV == NT
        prevtok[tid] = tok;
        atomicOr(&bm[tok >> 5], 1u << (tok & 31));
    }
    __syncthreads();

    // alignment: (rowbase + a) % 4 == 0 ; Vn % 4 == 1 -> a = (4 - (bk&3)) & 3
    const int a = (4 - (bk & 3)) & 3;
    const long b4 = (rowbase + a) >> 2;    // float4 index of row[a]

    // ---- phase 1: warm-up threshold over [a, a+WU) ----
    {
        float m = -3.0e38f;
#pragma unroll
        for (int j = 0; j < 4; j++) {
            float4 x = lp4[b4 + j * NT + tid];
            int v = a + 4 * (j * NT + tid);
            float p0 = ((bm[(v + 0) >> 5] >> ((v + 0) & 31)) & 1u) ? x.x - 128.0f : x.x;
            float p1 = ((bm[(v + 1) >> 5] >> ((v + 1) & 31)) & 1u) ? x.y - 128.0f : x.y;
            float p2 = ((bm[(v + 2) >> 5] >> ((v + 2) & 31)) & 1u) ? x.z - 128.0f : x.z;
            float p3 = ((bm[(v + 3) >> 5] >> ((v + 3) & 31)) & 1u) ? x.w - 128.0f : x.w;
            m = fmaxf(m, fmaxf(fmaxf(p0, p1), fmaxf(p2, p3)));
        }
        wmax[tid] = ford(m);
    }
    __syncthreads();
    {
        unsigned mo = wmax[tid];
        int rank = 0;
#pragma unroll 8
        for (int i = 0; i < NT; i++) {
            unsigned o = wmax[i];
            rank += (o > mo) || (o == mo && i < tid);
        }
        if (rank == 15) thr_s = finv(mo);
    }
    __syncthreads();
    const float thr = thr_s;

#define APPEND(X, VV)                                                         \
    if ((X) >= thr) {                                                         \
        int p = atomicAdd(&nbuf_s, 1);                                        \
        if (p < BUFSZ)                                                        \
            buf[p] = ((unsigned long long)__float_as_uint(X) << 32) |         \
                     (unsigned)(VV);                                          \
    }

    // ---- phase 2: barrier-free filtered sweep of the whole row ----
    // scalar prologue [0,a) and tail [a+4*nf4, Vn)
    const int nf4 = (Vn - a) >> 2;
    if (tid < a) { float x = row[tid]; APPEND(x, tid); }
    {
        const int tb = a + 4 * nf4;
        int v = tb + (tid & 3);
        if ((tid >> 2) == 8 && v < Vn) { float x = row[v]; APPEND(x, v); }
    }

    int i = tid;
    for (; i + 7 * NT < nf4; i += 8 * NT) {
        float4 x0 = lp4[b4 + i + 0 * NT];
        float4 x1 = lp4[b4 + i + 1 * NT];
        float4 x2 = lp4[b4 + i + 2 * NT];
        float4 x3 = lp4[b4 + i + 3 * NT];
        float4 x4 = lp4[b4 + i + 4 * NT];
        float4 x5 = lp4[b4 + i + 5 * NT];
        float4 x6 = lp4[b4 + i + 6 * NT];
        float4 x7 = lp4[b4 + i + 7 * NT];
        float m0 = fmaxf(fmaxf(x0.x, x0.y), fmaxf(x0.z, x0.w));
        float m1 = fmaxf(fmaxf(x1.x, x1.y), fmaxf(x1.z, x1.w));
        float m2 = fmaxf(fmaxf(x2.x, x2.y), fmaxf(x2.z, x2.w));
        float m3 = fmaxf(fmaxf(x3.x, x3.y), fmaxf(x3.z, x3.w));
        float m4 = fmaxf(fmaxf(x4.x, x4.y), fmaxf(x4.z, x4.w));
        float m5 = fmaxf(fmaxf(x5.x, x5.y), fmaxf(x5.z, x5.w));
        float m6 = fmaxf(fmaxf(x6.x, x6.y), fmaxf(x6.z, x6.w));
        float m7 = fmaxf(fmaxf(x7.x, x7.y), fmaxf(x7.z, x7.w));
        float gm = fmaxf(fmaxf(fmaxf(m0, m1), fmaxf(m2, m3)),
                         fmaxf(fmaxf(m4, m5), fmaxf(m6, m7)));
        if (gm >= thr) {
#define CHK4(X, J)                                                            \
            {                                                                 \
                int v = a + 4 * (i + (J) * NT);                               \
                APPEND((X).x, v + 0);                                         \
                APPEND((X).y, v + 1);                                         \
                APPEND((X).z, v + 2);                                         \
                APPEND((X).w, v + 3);                                         \
            }
            CHK4(x0, 0) CHK4(x1, 1) CHK4(x2, 2) CHK4(x3, 3)
            CHK4(x4, 4) CHK4(x5, 5) CHK4(x6, 6) CHK4(x7, 7)
#undef CHK4
        }
    }
    for (; i < nf4; i += NT) {
        float4 x = lp4[b4 + i];
        float m = fmaxf(fmaxf(x.x, x.y), fmaxf(x.z, x.w));
        if (m >= thr) {
            int v = a + 4 * i;
            APPEND(x.x, v + 0);
            APPEND(x.y, v + 1);
            APPEND(x.z, v + 2);
            APPEND(x.w, v + 3);
        }
    }
#undef APPEND
    __syncthreads();

    // ---- phase 3: parallel penalization, then serial top-16 merge ----
    const int n = (nbuf_s < BUFSZ) ? nbuf_s : BUFSZ;
    for (int j = tid; j < n; j += NT) {
        unsigned long long e = buf[j];
        unsigned v = (unsigned)e;
        float x = __uint_as_float((unsigned)(e >> 32));
        if (v == (unsigned)(Vn - 1)) x -= 1000.0f;
        if ((bm[v >> 5] >> (v & 31)) & 1u) {
            int cc = 0;
#pragma unroll 8
            for (int m = 0; m < NPREV; m++) cc += (prevtok[m] == (int)v);
            x -= 0.5f * (float)cc;
        }
        buf[j] = ((unsigned long long)ford(x) << 32) | (unsigned)(0xFFFFFFFFu - v);
    }
    __syncthreads();
    if (tid == 0) {
        int ntop = 0;
        for (int j = 0; j < n; j++) {
            unsigned long long key = buf[j];
            if (ntop < 16) {
                int p = ntop++;
                while (p > 0 && stop[p - 1] < key) { stop[p] = stop[p - 1]; p--; }
                stop[p] = key;
            } else if (key > stop[15]) {
                int p = 15;
                while (p > 0 && stop[p - 1] < key) { stop[p] = stop[p - 1]; p--; }
                stop[p] = key;
            }
        }
    }
    __syncthreads();
    if (tid < 16) g_cand[bk * 16 + tid] = stop[tid];
}

// ---------------- global top-16 over KxK candidates + seq outputs ----------------
__global__ __launch_bounds__(NT) void k_select(const float* __restrict__ lp,
                                               const int* __restrict__ beam_seq,
                                               const float* __restrict__ beam_lps,
                                               const float* __restrict__ sums,
                                               const int* __restrict__ d_t,
                                               float* __restrict__ out) {
    __shared__ unsigned long long skey[NT];
    __shared__ int sel_i[16];
    __shared__ float sel_v[16];
    __shared__ int q_s[16], tok_s[16];
    __shared__ float r_s[16];

    const int b = blockIdx.x, tid = threadIdx.x;
    {
        unsigned long long ck = g_cand[b * 256 + tid];
        float aug = finv((unsigned)(ck >> 32));
        float p = sums[b * Kn + (tid >> 4)] + aug;
        // flat index tid = k*K + c  -> matches jax reshape(B, K*K) tie order
        skey[tid] = ((unsigned long long)ford(p) << 32) | (unsigned)(0xFFFFFFFFu - (unsigned)tid);
    }
    __syncthreads();
    // rank-based selection: keys unique -> rank = #greater; rank<16 wins
    {
        unsigned long long mine = skey[tid];
        int rank = 0;
#pragma unroll 8
        for (int i = 0; i < NT; i++) rank += (skey[i] > mine);
        if (rank < 16) { sel_i[rank] = tid; sel_v[rank] = finv((unsigned)(mine >> 32)); }
    }
    __syncthreads();
    if (tid < 16) {
        int ii = sel_i[tid];
        int q = ii >> 4;
        unsigned long long ck = g_cand[b * 256 + ii];
        int tok = (int)(0xFFFFFFFFu - (unsigned)(ck & 0xFFFFFFFFull));
        float r = lp[(long)(b * Kn + q) * Vn + tok];   // unaugmented, exact
        if (tok == Vn - 1) r -= 1000.0f;
        q_s[tid] = q; tok_s[tid] = tok; r_s[tid] = r;
        g_q[b * Kn + tid] = q;
        out[OFF_SELP + b * Kn + tid] = sel_v[tid];
    }
    __syncthreads();
    const int t = d_t[0];   // low 32 bits: correct for i32 or little-endian i64
    for (int idx = tid; idx < Tn * Kn; idx += NT) {
        int tt = idx >> 4, k = idx & 15;
        float vs, vl;
        if (tt < t) {
            int q = q_s[k];
            vs = (float)beam_seq[(b * Tn + tt) * Kn + q];
            vl = beam_lps[(b * Tn + tt) * Kn + q];
        } else if (tt == t) {
            vs = (float)tok_s[k];
            vl = r_s[k];
        } else {
            vs = (float)beam_seq[(b * Tn + tt) * Kn + k];
            vl = beam_lps[(b * Tn + tt) * Kn + k];
        }
        out[(b * Tn + tt) * Kn + k] = vs;
        out[OFF_LPS + (b * Tn + tt) * Kn + k] = vl;
    }
}

// ---------------- state gather along beam dim (float4) ----------------
__global__ void k_state(const float4* __restrict__ st, float4* __restrict__ dst) {
    int idx = blockIdx.x * blockDim.x + threadIdx.x;   // over S*L*B*K*H/4 = 1048576
    int h4 = idx & (Hn / 4 - 1);
    int rowid = idx >> 7;              // H/4 = 128
    int k = rowid & (Kn - 1);
    int bsl = rowid >> 4;              // (s*L+l)*B + b
    int b = bsl & (Bn - 1);
    int q = __ldg(&g_q[b * Kn + k]);
    dst[idx] = st[((bsl << 4) + q) * (Hn / 4) + h4];
}

extern "C" void kernel_launch(void* const* d_in, const int* in_sizes, int n_in,
                              void* d_out, int out_size) {
    const float* lp   = (const float*)d_in[0];
    const int*   seq  = (const int*)d_in[1];
    const float* lps  = (const float*)d_in[2];
    const float* sums = (const float*)d_in[3];
    const float* st   = (const float*)d_in[4];
    const int*   prev = (const int*)d_in[5];
    const int*   dt   = (const int*)d_in[6];
    float* out = (float*)d_out;

    k_beam_topk<<<Bn * Kn, NT>>>(lp, prev);
    k_select<<<Bn, NT>>>(lp, seq, lps, sums, dt, out);
    k_state<<<(2 * 2 * Bn * Kn * (Hn / 4)) / NT, NT>>>((const float4*)st,
                                                       (float4*)(out + OFF_STATE));
}